// round 13
// baseline (speedup 1.0000x reference)
#include <cuda_runtime.h>
#include <cstdint>

#define B     64
#define F     3000
#define FSH   80
#define L     240000
#define EMPH  0.97f
#define NT    (B*F)
#define G     30          // frames emitted per group
#define NGRP  (F/G)       // 100 groups per batch
#define WARM  4           // warm-up frames: 0.97^(80*4) ~ 6e-5 state error
#define DEPTH 4           // cp.async ring depth
#define SLOT  128         // floats: 16 zero | 80 h | 16 an | 15 zero | 1 spare

// Scratch (static device arrays -- allocation-free per harness rules)
__device__ __align__(16) static float g_h [(size_t)NT*80];   // impulse responses
__device__ __align__(16) static float g_w [(size_t)NT*80];   // zero-state responses
__device__ __align__(16) static float g_an[(size_t)NT*16];   // an[j] = -a'[j+1], j=0..15

// ---------------------------------------------------------------------------
// Kernel 1: 2*NT threads; first NT compute an + h, second NT compute w.
// A warp owns 32 CONSECUTIVE frames; its global I/O spans are contiguous.
// Rows staged in smem stride-81 (conflict-free); flat copies coalesced.
// Tap sums use even/odd dual accumulators so the dependent-FMA chain is
// ~7 deep instead of 15 (recursion chain itself stays 1 FMA/sample).
// ---------------------------------------------------------------------------
__global__ void __launch_bounds__(128) k_prep(const float* __restrict__ e,
                                              const float* __restrict__ lpc)
{
    __shared__ float buf[4][32*81];
    int tid = blockIdx.x*128 + threadIdx.x;
    bool do_w = (tid >= NT);                 // uniform per block (NT % 128 == 0)
    int t2 = do_w ? tid - NT : tid;
    int wid  = threadIdx.x >> 5;
    int lane = threadIdx.x & 31;
    int wf0  = t2 - lane;                    // warp's first frame
    float* bw = buf[wid];

    float av[16];
    const float4* a4 = reinterpret_cast<const float4*>(lpc + (size_t)t2*16);
#pragma unroll
    for (int j = 0; j < 4; j++) {
        float4 t = a4[j];
        av[4*j+0]=t.x; av[4*j+1]=t.y; av[4*j+2]=t.z; av[4*j+3]=t.w;
    }

    // an[j] = -a'[j],  a'_j = a_j - EMPH*a_{j-1}  (a_0 = 1, a_16 = 0)
    float an[17];
    an[1] = EMPH - av[1];
#pragma unroll
    for (int j = 2; j <= 15; j++) an[j] = EMPH*av[j-1] - av[j];
    an[16] = EMPH*av[15];

    if (!do_w) {
        // ---- h half: store an, compute h into smem row ----
        float4* anout = reinterpret_cast<float4*>(g_an + (size_t)t2*16);
#pragma unroll
        for (int j = 0; j < 16; j += 4)
            anout[j>>2] = make_float4(an[j+1], an[j+2], an[j+3], an[j+4]);

        float* row = bw + lane*81;
        float hr[32];

        hr[0] = 1.f;
        row[0] = 1.f;
#pragma unroll
        for (int m = 1; m < 16; m++) {
            float pa = 0.f, pb = 0.f;
#pragma unroll
            for (int j = 2; j <= m; j++) {
                if (j & 1) pa = fmaf(an[j], hr[m-j], pa);
                else       pb = fmaf(an[j], hr[m-j], pb);
            }
            hr[m] = fmaf(an[1], hr[m-1], pa + pb);
            row[m] = hr[m];
        }
#pragma unroll 1
        for (int base = 16; base < 80; base += 32) {   // base ≡ 16 (mod 32)
#pragma unroll
            for (int u = 0; u < 32; u++) {
                int mi = 16 + u;                       // static ring phase
                float pa = 0.f, pb = 0.f;
#pragma unroll
                for (int j = 2; j <= 16; j += 2) {
                    pb = fmaf(an[j],   hr[(mi - j)     & 31], pb);
                    if (j < 16) pa = fmaf(an[j+1], hr[(mi - j - 1) & 31], pa);
                }
                float acch = fmaf(an[1], hr[(mi - 1) & 31], pa + pb);
                hr[mi & 31] = acch;
                row[base + u] = acch;
            }
        }
    } else {
        // ---- w half: coalesced e -> smem, in-place recursion e -> w ----
        const float* eg = e + (size_t)wf0*80;
#pragma unroll 8
        for (int it = 0; it < 80; it++) {
            int i = it*32 + lane;
            bw[i + i/80] = eg[i];                      // coalesced LDG.32
        }
        __syncwarp();

        float* row = bw + lane*81;
        float wr[16];
#pragma unroll
        for (int m = 0; m < 16; m++) {
            float pa = 0.f, pb = row[m];
#pragma unroll
            for (int j = 2; j <= m; j++) {
                if (j & 1) pa = fmaf(an[j], wr[m-j], pa);
                else       pb = fmaf(an[j], wr[m-j], pb);
            }
            wr[m] = (m >= 1) ? fmaf(an[1], wr[m-1], pa + pb) : pb;
            row[m] = wr[m];
        }
#pragma unroll 1
        for (int base = 16; base < 80; base += 16) {   // base ≡ 0 (mod 16)
#pragma unroll
            for (int u = 0; u < 16; u++) {
                int mi = u;                            // static ring phase
                float pa = 0.f, pb = row[base + u];
#pragma unroll
                for (int j = 2; j <= 16; j += 2) {
                    pb = fmaf(an[j],   wr[(mi - j)     & 15], pb);
                    if (j < 16) pa = fmaf(an[j+1], wr[(mi - j - 1) & 15], pa);
                }
                float accw = fmaf(an[1], wr[(mi - 1) & 15], pa + pb);
                wr[mi & 15] = accw;
                row[base + u] = accw;
            }
        }
    }
    __syncwarp();

    // coalesced copy-out of the warp's 2560-float span
    float* dst = (do_w ? g_w : g_h) + (size_t)wf0*80;
#pragma unroll 8
    for (int it = 0; it < 80; it++) {
        int i = it*32 + lane;
        dst[i] = bw[i + i/80];                         // coalesced STG.32
    }
}

// ---------------------------------------------------------------------------
// cp.async prefetch of one frame's h (80f, 16B chunks into words 16..95) + an
// (16f, 16B chunks into words 96..111) into a ring slot.
// Words 0..15 and 112..126 are zero pads (written once at init).
// ---------------------------------------------------------------------------
__device__ __forceinline__ void fused_prefetch(uint32_t slot, size_t fg, int lane, bool valid)
{
    if (valid) {
        if (lane < 20)
            asm volatile("cp.async.ca.shared.global [%0], [%1], 16;"
                         :: "r"(slot + 64u + (uint32_t)lane*16u),
                            "l"(g_h + fg*80 + lane*4) : "memory");
        if (lane < 4)
            asm volatile("cp.async.ca.shared.global [%0], [%1], 16;"
                         :: "r"(slot + 384u + (uint32_t)lane*16u),
                            "l"(g_an + fg*16 + lane*4) : "memory");
    }
    asm volatile("cp.async.commit_group;" ::: "memory");
}

// ---------------------------------------------------------------------------
// Kernel 2: fused scan + output. One warp per (batch, group of G frames),
// WARM warm-up frames from zero state (group 0 exact). Lane l owns outputs
// m = 4l..4l+3 (lanes 0..19; lanes 20..31 shadow lane 19). Shuffle-free loop:
//   state s[t] = z_prev[79-t] lives in per-warp smem rb[31-t]; read as two
//     broadcast LDS.128 (rb[24..31] for the low half, rb[16..23] for high)
//   r[k] = sum_t an_s[k+t] * s[t]       (zero-padded an -> no predicates)
//   z[m] = w[m] + sum_k r[k] h[m-k]     (5 overlapping float4 windows)
//   lanes 16..19 store z[64..79] back to rb for the next frame
// ---------------------------------------------------------------------------
__global__ void __launch_bounds__(128, 8) k_fused(float* __restrict__ out)
{
    __shared__ __align__(16) float ring[4][DEPTH][SLOT];
    __shared__ __align__(16) float rbuf[4][32];   // [0..15] r | [16..31] z-tail
    int w    = threadIdx.x >> 5;
    int lane = threadIdx.x & 31;
    size_t gg = (size_t)blockIdx.x*4 + w;
    int b = (int)(gg / NGRP), grp = (int)(gg - (size_t)b*NGRP);
    int f0 = grp * G;
    int fstart = (f0 >= WARM) ? f0 - WARM : 0;
    int warmcnt = f0 - fstart;
    int nfr = f0 + G - fstart;
    size_t fgbase = (size_t)b*F + fstart;
    uint32_t rbase = (uint32_t)__cvta_generic_to_shared(&ring[w][0][0]);
    float* rb = rbuf[w];

    // zero pads once: words 0..15 (left of h) and 112..126 (right of an)
    if (lane < 16) {
#pragma unroll
        for (int k = 0; k < DEPTH; k++) {
            ring[w][k][lane] = 0.f;
            if (lane < 15) ring[w][k][112 + lane] = 0.f;
        }
        rb[16 + lane] = 0.f;                 // initial state z_prev = 0
    }
    __syncwarp();

#pragma unroll
    for (int k = 0; k < DEPTH; k++)
        fused_prefetch(rbase + (uint32_t)k*SLOT*4u, fgbase + k, lane, k < nfr);

    int lane2 = (lane < 20) ? lane : 19;

    // w pipeline: float4 for frames j and j+1
    float4 wa, wb;
    {
        const float4* wp = reinterpret_cast<const float4*>(g_w + fgbase*80) + lane2;
        wa = wp[0];
        wb = (1 < nfr) ? wp[20] : make_float4(0.f,0.f,0.f,0.f);
    }

    float* outb = out + ((size_t)b*L + (size_t)fstart*FSH);
    int k16 = lane & 15;
    int tb  = (lane >> 4) << 3;          // 0 or 8
    int sbase = 7 - (tb >> 2);           // rb4 index of the half's top quad

#pragma unroll 1
    for (int j = 0; j < nfr; j++) {
        asm volatile("cp.async.wait_group %0;" :: "n"(DEPTH-1) : "memory");
        __syncwarp();
        const float* slot = &ring[w][j & (DEPTH-1)][0];
        const float* an_s = slot + 96;     // an_s[i] = an[i+1]; [16..30] = 0

        // prefetch w for frame j+2
        float4 wc = make_float4(0.f,0.f,0.f,0.f);
        if (j + 2 < nfr)
            wc = reinterpret_cast<const float4*>(g_w + (fgbase + j + 2)*80)[lane2];

        // r[k]: halves t=tb..tb+7, combine via xor-16. State read as two
        // broadcast LDS.128: s[tb+d] = rb[31-tb-d].
        const float4* rb4 = reinterpret_cast<const float4*>(rb);
        float4 sB = rb4[sbase];            // rb[31-tb-3 .. 31-tb]
        float4 sA = rb4[sbase - 1];        // rb[31-tb-7 .. 31-tb-4]
        float part;
        part = an_s[k16 + tb    ] * sB.w;
        part = fmaf(an_s[k16 + tb + 1], sB.z, part);
        part = fmaf(an_s[k16 + tb + 2], sB.y, part);
        part = fmaf(an_s[k16 + tb + 3], sB.x, part);
        part = fmaf(an_s[k16 + tb + 4], sA.w, part);
        part = fmaf(an_s[k16 + tb + 5], sA.z, part);
        part = fmaf(an_s[k16 + tb + 6], sA.y, part);
        part = fmaf(an_s[k16 + tb + 7], sA.x, part);
        float r = part + __shfl_xor_sync(0xffffffffu, part, 16);
        if (lane < 16) rb[lane] = r;
        __syncwarp();

        // conv: z[4l+c] = w + sum_k r[k] h[4l+c-k].
        // word(h[x]) = x+16; windows p_i = slot4[lane2+4-i]; for k-quad kg:
        // fb = p_kg, fa = p_{kg+1}; term(c,j) = rq[j]*(c>=j ? fb[c-j] : fa[4+c-j])
        const float4* slot4 = reinterpret_cast<const float4*>(slot);
        float4 qf[5];
        qf[0] = slot4[lane2 + 4];
        qf[1] = slot4[lane2 + 3];
        qf[2] = slot4[lane2 + 2];
        qf[3] = slot4[lane2 + 1];
        qf[4] = slot4[lane2    ];

        float a0 = wa.x, a1 = wa.y, a2 = wa.z, a3 = wa.w;
#pragma unroll
        for (int kg = 0; kg < 4; kg++) {
            float4 fb = qf[kg];
            float4 fa = qf[kg + 1];
            float4 rq = reinterpret_cast<const float4*>(rb)[kg];  // broadcast
            a0 = fmaf(rq.x, fb.x, a0); a0 = fmaf(rq.y, fa.w, a0);
            a0 = fmaf(rq.z, fa.z, a0); a0 = fmaf(rq.w, fa.y, a0);
            a1 = fmaf(rq.x, fb.y, a1); a1 = fmaf(rq.y, fb.x, a1);
            a1 = fmaf(rq.z, fa.w, a1); a1 = fmaf(rq.w, fa.z, a1);
            a2 = fmaf(rq.x, fb.z, a2); a2 = fmaf(rq.y, fb.y, a2);
            a2 = fmaf(rq.z, fb.x, a2); a2 = fmaf(rq.w, fa.w, a2);
            a3 = fmaf(rq.x, fb.w, a3); a3 = fmaf(rq.y, fb.z, a3);
            a3 = fmaf(rq.z, fb.y, a3); a3 = fmaf(rq.w, fb.x, a3);
        }

        if (j >= warmcnt && lane < 20)     // emit only the group's own frames
            reinterpret_cast<float4*>(outb + (size_t)j*FSH)[lane] =
                make_float4(a0, a1, a2, a3);

        // next state: lanes 16..19 hold z[64..79]; store z[4l+c] at rb[4l+c-48]
        if (lane >= 16 && lane < 20)
            reinterpret_cast<float4*>(rb + 16)[lane - 16] =
                make_float4(a0, a1, a2, a3);

        wa = wb; wb = wc;

        __syncwarp();                      // slot consumed + state published
        fused_prefetch(rbase + (uint32_t)(j & (DEPTH-1))*SLOT*4u,
                       fgbase + j + DEPTH, lane, (j + DEPTH) < nfr);
    }
}

// ---------------------------------------------------------------------------
extern "C" void kernel_launch(void* const* d_in, const int* in_sizes, int n_in,
                              void* d_out, int out_size)
{
    (void)in_sizes; (void)n_in; (void)out_size;
    const float* e   = (const float*)d_in[0];   // excit (B, L, 1)
    const float* lpc = (const float*)d_in[1];   // lpc_coef (B, F, 16)
    float* out = (float*)d_out;                 // (B, L, 1)

    k_prep <<<(2*NT)/128, 128>>>(e, lpc);
    k_fused<<<(B*NGRP)/4, 128>>>(out);
}

// round 14
// speedup vs baseline: 1.0271x; 1.0271x over previous
#include <cuda_runtime.h>
#include <cstdint>

#define B     64
#define F     3000
#define FSH   80
#define L     240000
#define EMPH  0.97f
#define NT    (B*F)
#define G     30          // frames emitted per group
#define NGRP  (F/G)       // 100 groups per batch
#define WARM  3           // warm-up frames: state err ~ 0.0875^3 = 6.7e-4 -> out ~5e-5
#define DEPTH 8           // cp.async ring depth (7-frame prefetch ~ 600 cyc cover)
#define SLOT  208         // floats: 16 zero | 80 h | 16 an | 16 zero | 80 w

// Scratch (static device arrays -- allocation-free per harness rules)
__device__ __align__(16) static float g_h [(size_t)NT*80];   // impulse responses
__device__ __align__(16) static float g_w [(size_t)NT*80];   // zero-state responses
__device__ __align__(16) static float g_an[(size_t)NT*16];   // an[j] = -a'[j+1], j=0..15

// ---------------------------------------------------------------------------
// Kernel 1 (R10 proven version): 2*NT threads; first NT compute an + h,
// second NT compute w. A warp owns 32 CONSECUTIVE frames; its global I/O
// spans are contiguous. Rows staged in smem stride-81 (conflict-free);
// flat copies are coalesced scalar LDG/STG.
// ---------------------------------------------------------------------------
__global__ void __launch_bounds__(128) k_prep(const float* __restrict__ e,
                                              const float* __restrict__ lpc)
{
    __shared__ float buf[4][32*81];
    int tid = blockIdx.x*128 + threadIdx.x;
    bool do_w = (tid >= NT);                 // uniform per block (NT % 128 == 0)
    int t2 = do_w ? tid - NT : tid;
    int wid  = threadIdx.x >> 5;
    int lane = threadIdx.x & 31;
    int wf0  = t2 - lane;                    // warp's first frame
    float* bw = buf[wid];

    float av[16];
    const float4* a4 = reinterpret_cast<const float4*>(lpc + (size_t)t2*16);
#pragma unroll
    for (int j = 0; j < 4; j++) {
        float4 t = a4[j];
        av[4*j+0]=t.x; av[4*j+1]=t.y; av[4*j+2]=t.z; av[4*j+3]=t.w;
    }

    // an[j] = -a'[j],  a'_j = a_j - EMPH*a_{j-1}  (a_0 = 1, a_16 = 0)
    float an[17];
    an[1] = EMPH - av[1];
#pragma unroll
    for (int j = 2; j <= 15; j++) an[j] = EMPH*av[j-1] - av[j];
    an[16] = EMPH*av[15];

    if (!do_w) {
        // ---- h half: store an, compute h into smem row ----
        float4* anout = reinterpret_cast<float4*>(g_an + (size_t)t2*16);
#pragma unroll
        for (int j = 0; j < 16; j += 4)
            anout[j>>2] = make_float4(an[j+1], an[j+2], an[j+3], an[j+4]);

        float* row = bw + lane*81;
        float hr[32];

        hr[0] = 1.f;
        row[0] = 1.f;
#pragma unroll
        for (int m = 1; m < 16; m++) {
            float part = 0.f;
#pragma unroll
            for (int j = 2; j <= m; j++) part = fmaf(an[j], hr[m-j], part);
            hr[m] = fmaf(an[1], hr[m-1], part);
            row[m] = hr[m];
        }
#pragma unroll 1
        for (int base = 16; base < 80; base += 32) {   // base ≡ 16 (mod 32)
#pragma unroll
            for (int u = 0; u < 32; u++) {
                int mi = 16 + u;                       // static ring phase
                float part = 0.f;
#pragma unroll
                for (int j = 2; j <= 16; j++)
                    part = fmaf(an[j], hr[(mi - j) & 31], part);
                float acch = fmaf(an[1], hr[(mi - 1) & 31], part);
                hr[mi & 31] = acch;
                row[base + u] = acch;
            }
        }
    } else {
        // ---- w half: coalesced e -> smem, in-place recursion e -> w ----
        const float* eg = e + (size_t)wf0*80;
#pragma unroll 8
        for (int it = 0; it < 80; it++) {
            int i = it*32 + lane;
            bw[i + i/80] = eg[i];                      // coalesced LDG.32
        }
        __syncwarp();

        float* row = bw + lane*81;
        float wr[16];
#pragma unroll
        for (int m = 0; m < 16; m++) {
            float part = row[m];
#pragma unroll
            for (int j = 2; j <= m; j++) part = fmaf(an[j], wr[m-j], part);
            wr[m] = (m >= 1) ? fmaf(an[1], wr[m-1], part) : part;
            row[m] = wr[m];
        }
#pragma unroll 1
        for (int base = 16; base < 80; base += 16) {   // base ≡ 0 (mod 16)
#pragma unroll
            for (int u = 0; u < 16; u++) {
                int mi = u;                            // static ring phase
                float part = row[base + u];
#pragma unroll
                for (int j = 2; j <= 16; j++)
                    part = fmaf(an[j], wr[(mi - j) & 15], part);
                float accw = fmaf(an[1], wr[(mi - 1) & 15], part);
                wr[mi & 15] = accw;
                row[base + u] = accw;
            }
        }
    }
    __syncwarp();

    // coalesced copy-out of the warp's 2560-float span
    float* dst = (do_w ? g_w : g_h) + (size_t)wf0*80;
#pragma unroll 8
    for (int it = 0; it < 80; it++) {
        int i = it*32 + lane;
        dst[i] = bw[i + i/80];                         // coalesced STG.32
    }
}

// ---------------------------------------------------------------------------
// cp.async prefetch of one frame's h (words 16..95), an (96..111) and w
// (128..207) into a ring slot, all 16B chunks.
// Words 0..15 and 112..127 are zero pads (written once at init).
// ---------------------------------------------------------------------------
__device__ __forceinline__ void fused_prefetch(uint32_t slot, size_t fg, int lane, bool valid)
{
    if (valid) {
        if (lane < 20) {
            asm volatile("cp.async.ca.shared.global [%0], [%1], 16;"
                         :: "r"(slot + 64u + (uint32_t)lane*16u),
                            "l"(g_h + fg*80 + lane*4) : "memory");
            asm volatile("cp.async.ca.shared.global [%0], [%1], 16;"
                         :: "r"(slot + 512u + (uint32_t)lane*16u),
                            "l"(g_w + fg*80 + lane*4) : "memory");
        }
        if (lane < 4)
            asm volatile("cp.async.ca.shared.global [%0], [%1], 16;"
                         :: "r"(slot + 384u + (uint32_t)lane*16u),
                            "l"(g_an + fg*16 + lane*4) : "memory");
    }
    asm volatile("cp.async.commit_group;" ::: "memory");
}

// ---------------------------------------------------------------------------
// Kernel 2: fused scan + output. One warp per (batch, group of G frames),
// WARM warm-up frames from zero state (group 0 exact). Lane l owns outputs
// m = 4l..4l+3 (lanes 0..19; lanes 20..31 shadow lane 19). Per frame:
//   state s[t] = z_prev[79-t] in per-warp smem rb[31-t] (2 broadcast LDS.128)
//   r[k] = sum_t an_s[k+t] * s[t]       (zero-padded an -> no predicates)
//   z[m] = w[m] + sum_k r[k] h[m-k]     (5 overlapping float4 h windows + w)
//   lanes 16..19 store z[64..79] back to rb for the next frame
// h, an AND w all arrive via the DEPTH-8 cp.async ring (7-frame prefetch).
// ---------------------------------------------------------------------------
__global__ void __launch_bounds__(128, 8) k_fused(float* __restrict__ out)
{
    __shared__ __align__(16) float ring[4][DEPTH][SLOT];
    __shared__ __align__(16) float rbuf[4][32];   // [0..15] r | [16..31] z-tail
    int w    = threadIdx.x >> 5;
    int lane = threadIdx.x & 31;
    size_t gg = (size_t)blockIdx.x*4 + w;
    int b = (int)(gg / NGRP), grp = (int)(gg - (size_t)b*NGRP);
    int f0 = grp * G;
    int fstart = (f0 >= WARM) ? f0 - WARM : 0;
    int warmcnt = f0 - fstart;
    int nfr = f0 + G - fstart;
    size_t fgbase = (size_t)b*F + fstart;
    uint32_t rbase = (uint32_t)__cvta_generic_to_shared(&ring[w][0][0]);
    float* rb = rbuf[w];

    // zero pads once: words 0..15 (left of h) and 112..127 (right of an)
    if (lane < 16) {
#pragma unroll
        for (int k = 0; k < DEPTH; k++) {
            ring[w][k][lane]       = 0.f;
            ring[w][k][112 + lane] = 0.f;
        }
        rb[16 + lane] = 0.f;                 // initial state z_prev = 0
    }
    __syncwarp();

#pragma unroll
    for (int k = 0; k < DEPTH; k++)
        fused_prefetch(rbase + (uint32_t)k*SLOT*4u, fgbase + k, lane, k < nfr);

    int lane2 = (lane < 20) ? lane : 19;

    float* outb = out + ((size_t)b*L + (size_t)fstart*FSH);
    int k16 = lane & 15;
    int tb  = (lane >> 4) << 3;          // 0 or 8
    int sbase = 7 - (tb >> 2);           // rb4 index of the half's top quad

#pragma unroll 1
    for (int j = 0; j < nfr; j++) {
        asm volatile("cp.async.wait_group %0;" :: "n"(DEPTH-1) : "memory");
        __syncwarp();
        const float* slot = &ring[w][j & (DEPTH-1)][0];
        const float* an_s = slot + 96;     // an_s[i] = an[i+1]; [16..31] = 0

        // r[k]: halves t=tb..tb+7, combine via xor-16. State read as two
        // broadcast LDS.128: s[tb+d] = rb[31-tb-d].
        const float4* rb4 = reinterpret_cast<const float4*>(rb);
        float4 sB = rb4[sbase];            // rb[31-tb-3 .. 31-tb]
        float4 sA = rb4[sbase - 1];        // rb[31-tb-7 .. 31-tb-4]
        float part;
        part = an_s[k16 + tb    ] * sB.w;
        part = fmaf(an_s[k16 + tb + 1], sB.z, part);
        part = fmaf(an_s[k16 + tb + 2], sB.y, part);
        part = fmaf(an_s[k16 + tb + 3], sB.x, part);
        part = fmaf(an_s[k16 + tb + 4], sA.w, part);
        part = fmaf(an_s[k16 + tb + 5], sA.z, part);
        part = fmaf(an_s[k16 + tb + 6], sA.y, part);
        part = fmaf(an_s[k16 + tb + 7], sA.x, part);
        float r = part + __shfl_xor_sync(0xffffffffu, part, 16);
        if (lane < 16) rb[lane] = r;
        __syncwarp();

        // conv: z[4l+c] = w[4l+c] + sum_k r[k] h[4l+c-k].
        // word(h[x]) = x+16; windows p_i = slot4[lane2+4-i]; for k-quad kg:
        // fb = p_kg, fa = p_{kg+1}; term(c,j) = rq[j]*(c>=j ? fb[c-j] : fa[4+c-j])
        const float4* slot4 = reinterpret_cast<const float4*>(slot);
        float4 wa = slot4[32 + lane2];     // w quad (words 128..207)
        float4 qf[5];
        qf[0] = slot4[lane2 + 4];
        qf[1] = slot4[lane2 + 3];
        qf[2] = slot4[lane2 + 2];
        qf[3] = slot4[lane2 + 1];
        qf[4] = slot4[lane2    ];

        float a0 = wa.x, a1 = wa.y, a2 = wa.z, a3 = wa.w;
#pragma unroll
        for (int kg = 0; kg < 4; kg++) {
            float4 fb = qf[kg];
            float4 fa = qf[kg + 1];
            float4 rq = reinterpret_cast<const float4*>(rb)[kg];  // broadcast
            a0 = fmaf(rq.x, fb.x, a0); a0 = fmaf(rq.y, fa.w, a0);
            a0 = fmaf(rq.z, fa.z, a0); a0 = fmaf(rq.w, fa.y, a0);
            a1 = fmaf(rq.x, fb.y, a1); a1 = fmaf(rq.y, fb.x, a1);
            a1 = fmaf(rq.z, fa.w, a1); a1 = fmaf(rq.w, fa.z, a1);
            a2 = fmaf(rq.x, fb.z, a2); a2 = fmaf(rq.y, fb.y, a2);
            a2 = fmaf(rq.z, fb.x, a2); a2 = fmaf(rq.w, fa.w, a2);
            a3 = fmaf(rq.x, fb.w, a3); a3 = fmaf(rq.y, fb.z, a3);
            a3 = fmaf(rq.z, fb.y, a3); a3 = fmaf(rq.w, fb.x, a3);
        }

        if (j >= warmcnt && lane < 20)     // emit only the group's own frames
            reinterpret_cast<float4*>(outb + (size_t)j*FSH)[lane] =
                make_float4(a0, a1, a2, a3);

        // next state: lanes 16..19 hold z[64..79]; store z[4l+c] at rb[4l+c-48]
        if (lane >= 16 && lane < 20)
            reinterpret_cast<float4*>(rb + 16)[lane - 16] =
                make_float4(a0, a1, a2, a3);

        __syncwarp();                      // slot consumed + state published
        fused_prefetch(rbase + (uint32_t)(j & (DEPTH-1))*SLOT*4u,
                       fgbase + j + DEPTH, lane, (j + DEPTH) < nfr);
    }
}

// ---------------------------------------------------------------------------
extern "C" void kernel_launch(void* const* d_in, const int* in_sizes, int n_in,
                              void* d_out, int out_size)
{
    (void)in_sizes; (void)n_in; (void)out_size;
    const float* e   = (const float*)d_in[0];   // excit (B, L, 1)
    const float* lpc = (const float*)d_in[1];   // lpc_coef (B, F, 16)
    float* out = (float*)d_out;                 // (B, L, 1)

    k_prep <<<(2*NT)/128, 128>>>(e, lpc);
    k_fused<<<(B*NGRP)/4, 128>>>(out);
}